// round 2
// baseline (speedup 1.0000x reference)
#include <cuda_runtime.h>
#include <math.h>

#define N_NODES 100000
#define N_EDGES 200000
#define NNZ_    1600000
#define INC 128
#define OUTC 128
#define STAR_ 64
#define KTOT 192

// ---------------- device scratch (allocation-free) ----------------
__device__ float g_Xfeat[(size_t)N_NODES * OUTC];   // 51.2 MB
__device__ float g_scores[N_NODES];
__device__ float g_w[NNZ_];                          // exp(leaky(score)) per nnz
__device__ float g_ssum[N_EDGES];                    // softmax denominators
__device__ float g_cnt[N_NODES];                     // node in-degree counts
__device__ float g_Yv2e[(size_t)N_EDGES * OUTC];     // 102.4 MB
__device__ float g_Y[(size_t)N_EDGES * OUTC];        // 102.4 MB
__device__ float g_num[(size_t)N_NODES * OUTC];      // 51.2 MB

// ---------------- helpers ----------------
__device__ __forceinline__ void red_add_v4(float* p, float4 v) {
    asm volatile("red.global.add.v4.f32 [%0], {%1, %2, %3, %4};"
                 :: "l"(p), "f"(v.x), "f"(v.y), "f"(v.z), "f"(v.w) : "memory");
}

__device__ __forceinline__ float elu1(float x) {
    return x > 0.f ? x : expm1f(x);
}

// ---------------- Kernel 1: X_init = X@Wx+bx ; X_feat = X@Wv+bv ----------------
// Block: 64 rows x 128 cols, 256 threads, each thread 8 rows x 4 cols per matrix.
// Smem: sXT[128][72] transposed X tile, sWx[128][132], sWv[128][132].
__global__ __launch_bounds__(256, 1) void gemm_x_kernel(
    const float* __restrict__ X, const float* __restrict__ Wx, const float* __restrict__ bx,
    const float* __restrict__ Wv, const float* __restrict__ bv,
    float* __restrict__ Xinit)
{
    extern __shared__ float sm[];
    float* sXT = sm;                 // 128*72
    float* sWx = sm + 128 * 72;      // 128*132
    float* sWv = sWx + 128 * 132;    // 128*132

    const int tx = threadIdx.x;
    const int n0 = blockIdx.x * 64;

    // load X tile (64 rows x 128 cols) transposed
    #pragma unroll
    for (int it = 0; it < 8; it++) {
        int idx = tx + it * 256;          // 0..2047
        int row = idx >> 5;               // 0..63
        int kq  = idx & 31;
        int n = n0 + row;
        float4 v = make_float4(0.f, 0.f, 0.f, 0.f);
        if (n < N_NODES) v = *(const float4*)&X[(size_t)n * INC + kq * 4];
        sXT[(kq * 4 + 0) * 72 + row] = v.x;
        sXT[(kq * 4 + 1) * 72 + row] = v.y;
        sXT[(kq * 4 + 2) * 72 + row] = v.z;
        sXT[(kq * 4 + 3) * 72 + row] = v.w;
    }
    // load both weight matrices
    #pragma unroll
    for (int it = 0; it < 16; it++) {
        int idx = tx + it * 256;          // 0..4095
        int k  = idx >> 5;
        int cq = idx & 31;
        *(float4*)&sWx[k * 132 + cq * 4] = *(const float4*)&Wx[k * OUTC + cq * 4];
        *(float4*)&sWv[k * 132 + cq * 4] = *(const float4*)&Wv[k * OUTC + cq * 4];
    }
    __syncthreads();

    const int c0 = (tx & 31) * 4;
    const int r0 = (tx >> 5) * 8;

    float4 ax[8], av[8];
    #pragma unroll
    for (int i = 0; i < 8; i++) {
        ax[i] = make_float4(0.f, 0.f, 0.f, 0.f);
        av[i] = make_float4(0.f, 0.f, 0.f, 0.f);
    }

    #pragma unroll 4
    for (int k = 0; k < 128; k++) {
        float4 wx4 = *(float4*)&sWx[k * 132 + c0];
        float4 wv4 = *(float4*)&sWv[k * 132 + c0];
        float4 xa = *(float4*)&sXT[k * 72 + r0];
        float4 xb = *(float4*)&sXT[k * 72 + r0 + 4];
        float xs[8] = {xa.x, xa.y, xa.z, xa.w, xb.x, xb.y, xb.z, xb.w};
        #pragma unroll
        for (int i = 0; i < 8; i++) {
            float x = xs[i];
            ax[i].x += x * wx4.x; ax[i].y += x * wx4.y; ax[i].z += x * wx4.z; ax[i].w += x * wx4.w;
            av[i].x += x * wv4.x; av[i].y += x * wv4.y; av[i].z += x * wv4.z; av[i].w += x * wv4.w;
        }
    }

    float4 bx4 = *(const float4*)&bx[c0];
    float4 bv4 = *(const float4*)&bv[c0];
    #pragma unroll
    for (int i = 0; i < 8; i++) {
        int n = n0 + r0 + i;
        if (n < N_NODES) {
            float4 o = make_float4(ax[i].x + bx4.x, ax[i].y + bx4.y, ax[i].z + bx4.z, ax[i].w + bx4.w);
            *(float4*)&Xinit[(size_t)n * OUTC + c0] = o;
            float4 f = make_float4(av[i].x + bv4.x, av[i].y + bv4.y, av[i].z + bv4.z, av[i].w + bv4.w);
            *(float4*)&g_Xfeat[(size_t)n * OUTC + c0] = f;
        }
    }
}

// ---------------- scores = X_feat @ a_vec  (warp per node) ----------------
__global__ __launch_bounds__(256) void scores_kernel(const float* __restrict__ a)
{
    int w = (blockIdx.x * 256 + threadIdx.x) >> 5;   // node id
    int lane = threadIdx.x & 31;
    if (w >= N_NODES) return;
    float4 xf = *(const float4*)&g_Xfeat[(size_t)w * OUTC + lane * 4];
    float4 a4 = *(const float4*)&a[lane * 4];
    float s = xf.x * a4.x + xf.y * a4.y + xf.z * a4.z + xf.w * a4.w;
    #pragma unroll
    for (int off = 16; off; off >>= 1) s += __shfl_down_sync(0xffffffffu, s, off);
    if (lane == 0) g_scores[w] = s;
}

// ---------------- pass A: exp(leaky(score[V])), denom per edge, node counts ----------------
__global__ __launch_bounds__(256) void passA_kernel(const int* __restrict__ V, const int* __restrict__ E)
{
    int i = blockIdx.x * 256 + threadIdx.x;          // exact: 6250*256 = NNZ
    int v = V[i];
    int e = E[i];
    float s = g_scores[v];
    s = s > 0.f ? s : 0.2f * s;
    float w = expf(s);
    g_w[i] = w;
    atomicAdd(&g_ssum[e], w);
    atomicAdd(&g_cnt[v], 1.0f);
}

// ---------------- pass B: Y_v2e[e] += (w_i/ssum[e]) * X_feat[v_i]  (warp per nnz) ----------------
__global__ __launch_bounds__(256) void passB_kernel(const int* __restrict__ V, const int* __restrict__ E)
{
    int i = blockIdx.x * 8 + (threadIdx.x >> 5);     // exact: 200000*8 = NNZ
    int lane = threadIdx.x & 31;
    int v = __ldg(&V[i]);
    int e = __ldg(&E[i]);
    float w = g_w[i] / g_ssum[e];
    float4 xf = *(const float4*)&g_Xfeat[(size_t)v * OUTC + lane * 4];
    xf.x *= w; xf.y *= w; xf.z *= w; xf.w *= w;
    red_add_v4(&g_Yv2e[(size_t)e * OUTC + lane * 4], xf);
}

// ---------------- GEMM2: Y = [elu(Yv2e), S] @ Wt + bt ----------------
// Block: 64 edge-rows x 128 cols, K=192.
__global__ __launch_bounds__(256, 1) void gemm2_kernel(
    const float* __restrict__ S, const float* __restrict__ Wt, const float* __restrict__ bt)
{
    extern __shared__ float sm[];
    float* sMT = sm;               // 192*72 transposed message tile
    float* sW  = sm + 192 * 72;    // 192*132

    const int tx = threadIdx.x;
    const int e0 = blockIdx.x * 64;  // 3125 blocks * 64 = 200000 exact

    #pragma unroll
    for (int it = 0; it < 12; it++) {
        int idx = tx + it * 256;       // 0..3071 = 64 rows * 48 float4
        int row = idx / 48;
        int kq  = idx % 48;
        float4 v;
        if (kq < 32) {
            v = *(const float4*)&g_Yv2e[(size_t)(e0 + row) * OUTC + kq * 4];
            v.x = elu1(v.x); v.y = elu1(v.y); v.z = elu1(v.z); v.w = elu1(v.w);
        } else {
            v = *(const float4*)&S[(size_t)(e0 + row) * STAR_ + (kq - 32) * 4];
        }
        int k = kq * 4;
        sMT[(k + 0) * 72 + row] = v.x;
        sMT[(k + 1) * 72 + row] = v.y;
        sMT[(k + 2) * 72 + row] = v.z;
        sMT[(k + 3) * 72 + row] = v.w;
    }
    #pragma unroll
    for (int it = 0; it < 24; it++) {
        int idx = tx + it * 256;       // 0..6143 = 192*32
        int k  = idx >> 5;
        int cq = idx & 31;
        *(float4*)&sW[k * 132 + cq * 4] = *(const float4*)&Wt[k * OUTC + cq * 4];
    }
    __syncthreads();

    const int c0 = (tx & 31) * 4;
    const int r0 = (tx >> 5) * 8;

    float4 acc[8];
    #pragma unroll
    for (int i = 0; i < 8; i++) acc[i] = make_float4(0.f, 0.f, 0.f, 0.f);

    #pragma unroll 4
    for (int k = 0; k < KTOT; k++) {
        float4 w4 = *(float4*)&sW[k * 132 + c0];
        float4 xa = *(float4*)&sMT[k * 72 + r0];
        float4 xb = *(float4*)&sMT[k * 72 + r0 + 4];
        float xs[8] = {xa.x, xa.y, xa.z, xa.w, xb.x, xb.y, xb.z, xb.w};
        #pragma unroll
        for (int i = 0; i < 8; i++) {
            float x = xs[i];
            acc[i].x += x * w4.x; acc[i].y += x * w4.y; acc[i].z += x * w4.z; acc[i].w += x * w4.w;
        }
    }

    float4 bt4 = *(const float4*)&bt[c0];
    #pragma unroll
    for (int i = 0; i < 8; i++) {
        int e = e0 + r0 + i;
        float4 o = make_float4(acc[i].x + bt4.x, acc[i].y + bt4.y, acc[i].z + bt4.z, acc[i].w + bt4.w);
        *(float4*)&g_Y[(size_t)e * OUTC + c0] = o;
    }
}

// ---------------- pass C: num[v] += Y[e]  (warp per nnz) ----------------
__global__ __launch_bounds__(256) void passC_kernel(const int* __restrict__ V, const int* __restrict__ E)
{
    int i = blockIdx.x * 8 + (threadIdx.x >> 5);
    int lane = threadIdx.x & 31;
    int v = __ldg(&V[i]);
    int e = __ldg(&E[i]);
    float4 y = *(const float4*)&g_Y[(size_t)e * OUTC + lane * 4];
    red_add_v4(&g_num[(size_t)v * OUTC + lane * 4], y);
}

// ---------------- finalize: out = elu(num/max(cnt,1)) + X_init ----------------
__global__ __launch_bounds__(256) void finalize_kernel(float* __restrict__ out)
{
    int idx = blockIdx.x * 256 + threadIdx.x;     // 12500*256 = 3.2M = N_NODES*32
    int n  = idx >> 5;
    int c0 = (idx & 31) * 4;
    float cnt = g_cnt[n];
    float inv = 1.0f / fmaxf(cnt, 1.0f);
    float4 v = *(const float4*)&g_num[(size_t)n * OUTC + c0];
    v.x = elu1(v.x * inv); v.y = elu1(v.y * inv); v.z = elu1(v.z * inv); v.w = elu1(v.w * inv);
    float4 o = *(const float4*)&out[(size_t)n * OUTC + c0];
    o.x += v.x; o.y += v.y; o.z += v.z; o.w += v.w;
    *(float4*)&out[(size_t)n * OUTC + c0] = o;
}

// ---------------- launch ----------------
extern "C" void kernel_launch(void* const* d_in, const int* in_sizes, int n_in,
                              void* d_out, int out_size)
{
    const float* X  = (const float*)d_in[0];
    const int*   V  = (const int*)d_in[1];
    const int*   E  = (const int*)d_in[2];
    const float* S  = (const float*)d_in[3];
    const float* Wx = (const float*)d_in[4];
    const float* bx = (const float*)d_in[5];
    const float* Wv = (const float*)d_in[6];
    const float* bv = (const float*)d_in[7];
    const float* a  = (const float*)d_in[8];
    const float* Wt = (const float*)d_in[9];
    const float* bt = (const float*)d_in[10];
    float* out = (float*)d_out;

    void *p_ssum, *p_cnt, *p_yv2e, *p_num;
    cudaGetSymbolAddress(&p_ssum, g_ssum);
    cudaGetSymbolAddress(&p_cnt,  g_cnt);
    cudaGetSymbolAddress(&p_yv2e, g_Yv2e);
    cudaGetSymbolAddress(&p_num,  g_num);
    cudaMemsetAsync(p_ssum, 0, (size_t)N_EDGES * sizeof(float));
    cudaMemsetAsync(p_cnt,  0, (size_t)N_NODES * sizeof(float));
    cudaMemsetAsync(p_yv2e, 0, (size_t)N_EDGES * OUTC * sizeof(float));
    cudaMemsetAsync(p_num,  0, (size_t)N_NODES * OUTC * sizeof(float));

    const int smem1 = (128 * 72 + 2 * 128 * 132) * (int)sizeof(float);  // 172032
    const int smem2 = (192 * 72 + 192 * 132) * (int)sizeof(float);      // 156672
    cudaFuncSetAttribute(gemm_x_kernel, cudaFuncAttributeMaxDynamicSharedMemorySize, smem1);
    cudaFuncSetAttribute(gemm2_kernel,  cudaFuncAttributeMaxDynamicSharedMemorySize, smem2);

    gemm_x_kernel<<<1563, 256, smem1>>>(X, Wx, bx, Wv, bv, out);
    scores_kernel<<<12500, 256>>>(a);
    passA_kernel<<<6250, 256>>>(V, E);
    passB_kernel<<<200000, 256>>>(V, E);
    gemm2_kernel<<<3125, 256, smem2>>>(S, Wt, bt);
    passC_kernel<<<200000, 256>>>(V, E);
    finalize_kernel<<<12500, 256>>>(out);
}

// round 4
// speedup vs baseline: 1.4237x; 1.4237x over previous
#include <cuda_runtime.h>
#include <math.h>

#define N_NODES 100000
#define N_EDGES 200000
#define NNZ_    1600000
#define INC 128
#define OUTC 128
#define STAR_ 64
#define KTOT 192

// ---------------- device scratch (allocation-free) ----------------
__device__ float g_Xfeat[(size_t)N_NODES * OUTC];   // 51.2 MB
__device__ float g_scores[N_NODES];
__device__ float g_Yv2e[(size_t)N_EDGES * OUTC];     // 102.4 MB (stores elu'd rows)
__device__ float g_Y[(size_t)N_EDGES * OUTC];        // 102.4 MB

// CSR by edge (segments of nnz grouped by E), payload = V
__device__ int g_histE[N_EDGES];
__device__ int g_baseE[N_EDGES];
__device__ int g_curE[N_EDGES];
__device__ int g_csrE_v[NNZ_];
// CSR by node (segments of nnz grouped by V), payload = E
__device__ int g_histV[N_NODES];
__device__ int g_baseV[N_NODES];
__device__ int g_curV[N_NODES];
__device__ int g_csrV_e[NNZ_];
__device__ int g_alloc_ctr[2];

// ---------------- helpers ----------------
__device__ __forceinline__ float elu1(float x) {
    return x > 0.f ? x : expm1f(x);
}

// ---------------- Kernel 1: X_init = X@Wx+bx ; X_feat = X@Wv+bv ; scores = X_feat@a ----------------
__global__ __launch_bounds__(256, 1) void gemm_x_kernel(
    const float* __restrict__ X, const float* __restrict__ Wx, const float* __restrict__ bx,
    const float* __restrict__ Wv, const float* __restrict__ bv, const float* __restrict__ a_vec,
    float* __restrict__ Xinit)
{
    extern __shared__ float sm[];
    float* sXT = sm;                 // 128*72
    float* sWx = sm + 128 * 72;      // 128*132
    float* sWv = sWx + 128 * 132;    // 128*132

    const int tx = threadIdx.x;
    const int n0 = blockIdx.x * 64;

    #pragma unroll
    for (int it = 0; it < 8; it++) {
        int idx = tx + it * 256;
        int row = idx >> 5;
        int kq  = idx & 31;
        int n = n0 + row;
        float4 v = make_float4(0.f, 0.f, 0.f, 0.f);
        if (n < N_NODES) v = *(const float4*)&X[(size_t)n * INC + kq * 4];
        sXT[(kq * 4 + 0) * 72 + row] = v.x;
        sXT[(kq * 4 + 1) * 72 + row] = v.y;
        sXT[(kq * 4 + 2) * 72 + row] = v.z;
        sXT[(kq * 4 + 3) * 72 + row] = v.w;
    }
    #pragma unroll
    for (int it = 0; it < 16; it++) {
        int idx = tx + it * 256;
        int k  = idx >> 5;
        int cq = idx & 31;
        *(float4*)&sWx[k * 132 + cq * 4] = *(const float4*)&Wx[k * OUTC + cq * 4];
        *(float4*)&sWv[k * 132 + cq * 4] = *(const float4*)&Wv[k * OUTC + cq * 4];
    }
    __syncthreads();

    const int c0 = (tx & 31) * 4;
    const int r0 = (tx >> 5) * 8;

    float4 ax[8], av[8];
    #pragma unroll
    for (int i = 0; i < 8; i++) {
        ax[i] = make_float4(0.f, 0.f, 0.f, 0.f);
        av[i] = make_float4(0.f, 0.f, 0.f, 0.f);
    }

    #pragma unroll 4
    for (int k = 0; k < 128; k++) {
        float4 wx4 = *(float4*)&sWx[k * 132 + c0];
        float4 wv4 = *(float4*)&sWv[k * 132 + c0];
        float4 xa = *(float4*)&sXT[k * 72 + r0];
        float4 xb = *(float4*)&sXT[k * 72 + r0 + 4];
        float xs[8] = {xa.x, xa.y, xa.z, xa.w, xb.x, xb.y, xb.z, xb.w};
        #pragma unroll
        for (int i = 0; i < 8; i++) {
            float x = xs[i];
            ax[i].x += x * wx4.x; ax[i].y += x * wx4.y; ax[i].z += x * wx4.z; ax[i].w += x * wx4.w;
            av[i].x += x * wv4.x; av[i].y += x * wv4.y; av[i].z += x * wv4.z; av[i].w += x * wv4.w;
        }
    }

    float4 bx4 = *(const float4*)&bx[c0];
    float4 bv4 = *(const float4*)&bv[c0];
    float4 aa4 = *(const float4*)&a_vec[c0];
    const int lane = tx & 31;
    #pragma unroll
    for (int i = 0; i < 8; i++) {
        int n = n0 + r0 + i;
        if (n < N_NODES) {   // warp-uniform guard (r0 constant per warp)
            float4 o = make_float4(ax[i].x + bx4.x, ax[i].y + bx4.y, ax[i].z + bx4.z, ax[i].w + bx4.w);
            *(float4*)&Xinit[(size_t)n * OUTC + c0] = o;
            float4 f = make_float4(av[i].x + bv4.x, av[i].y + bv4.y, av[i].z + bv4.z, av[i].w + bv4.w);
            *(float4*)&g_Xfeat[(size_t)n * OUTC + c0] = f;
            // fused score: dot(X_feat_row, a_vec)
            float part = f.x * aa4.x + f.y * aa4.y + f.z * aa4.z + f.w * aa4.w;
            #pragma unroll
            for (int off = 16; off; off >>= 1) part += __shfl_down_sync(0xffffffffu, part, off);
            if (lane == 0) g_scores[n] = part;
        }
    }
}

// ---------------- histogram: deg per edge + deg per node ----------------
__global__ __launch_bounds__(256) void hist_kernel(const int* __restrict__ V, const int* __restrict__ E)
{
    int i = blockIdx.x * 256 + threadIdx.x;     // 6250*256 = NNZ exact
    atomicAdd(&g_histE[__ldg(&E[i])], 1);
    atomicAdd(&g_histV[__ldg(&V[i])], 1);
}

// ---------------- segment-base allocation: contiguous chunk per segment ----------------
__global__ __launch_bounds__(256) void alloc_kernel(const int* __restrict__ hist,
        int* __restrict__ base, int* __restrict__ cur, int len, int ctr_idx)
{
    __shared__ int s_warp[8];
    __shared__ int s_base;
    const int t = threadIdx.x;
    const int i = blockIdx.x * 256 + t;
    const int lane = t & 31, wid = t >> 5;
    int v = (i < len) ? hist[i] : 0;
    int x = v;
    #pragma unroll
    for (int off = 1; off < 32; off <<= 1) {
        int y = __shfl_up_sync(0xffffffffu, x, off);
        if (lane >= off) x += y;
    }
    if (lane == 31) s_warp[wid] = x;
    __syncthreads();
    if (wid == 0) {
        int orig = (lane < 8) ? s_warp[lane] : 0;
        int s = orig;
        #pragma unroll
        for (int off = 1; off < 8; off <<= 1) {
            int y = __shfl_up_sync(0xffffffffu, s, off);
            if (lane >= off) s += y;
        }
        if (lane == 7) s_base = atomicAdd(&g_alloc_ctr[ctr_idx], s);  // s = block total
        if (lane < 8) s_warp[lane] = s - orig;                        // exclusive warp prefix
    }
    __syncthreads();
    if (i < len) {
        int excl = (x - v) + s_warp[wid] + s_base;
        base[i] = excl;
        cur[i]  = excl;
    }
}

// ---------------- scatter nnz into both CSRs ----------------
__global__ __launch_bounds__(256) void scatter_kernel(const int* __restrict__ V, const int* __restrict__ E)
{
    int i = blockIdx.x * 256 + threadIdx.x;     // NNZ exact
    int v = __ldg(&V[i]);
    int e = __ldg(&E[i]);
    int pE = atomicAdd(&g_curE[e], 1);
    g_csrE_v[pE] = v;
    int pV = atomicAdd(&g_curV[v], 1);
    g_csrV_e[pV] = e;
}

// ---------------- edge aggregation: Yv2e[e] = elu( sum_i w_i*Xfeat[v_i] / sum_i w_i ) ----------------
// warp per edge; 25000 blocks * 8 warps = 200000 exact
__global__ __launch_bounds__(256) void edge_agg_kernel()
{
    const int e = blockIdx.x * 8 + (threadIdx.x >> 5);
    const int lane = threadIdx.x & 31;
    const int base = g_baseE[e];
    const int deg  = g_histE[e];
    float4 acc = make_float4(0.f, 0.f, 0.f, 0.f);
    float denom = 0.f;
    for (int j = 0; j < deg; j++) {
        int v = __ldg(&g_csrE_v[base + j]);           // warp-broadcast
        float s = g_scores[v];
        s = s > 0.f ? s : 0.2f * s;
        float w = expf(s);
        denom += w;
        float4 xf = *(const float4*)&g_Xfeat[(size_t)v * OUTC + lane * 4];
        acc.x += w * xf.x; acc.y += w * xf.y; acc.z += w * xf.z; acc.w += w * xf.w;
    }
    float inv = (deg > 0) ? (1.f / denom) : 0.f;
    float4 o;
    o.x = elu1(acc.x * inv); o.y = elu1(acc.y * inv);
    o.z = elu1(acc.z * inv); o.w = elu1(acc.w * inv);
    *(float4*)&g_Yv2e[(size_t)e * OUTC + lane * 4] = o;
}

// ---------------- GEMM2: Y = [Yv2e(already elu'd), S] @ Wt + bt ----------------
__global__ __launch_bounds__(256, 1) void gemm2_kernel(
    const float* __restrict__ S, const float* __restrict__ Wt, const float* __restrict__ bt)
{
    extern __shared__ float sm[];
    float* sMT = sm;               // 192*72
    float* sW  = sm + 192 * 72;    // 192*132

    const int tx = threadIdx.x;
    const int e0 = blockIdx.x * 64;

    #pragma unroll
    for (int it = 0; it < 12; it++) {
        int idx = tx + it * 256;
        int row = idx / 48;
        int kq  = idx % 48;
        float4 v;
        if (kq < 32) {
            v = *(const float4*)&g_Yv2e[(size_t)(e0 + row) * OUTC + kq * 4];
        } else {
            v = *(const float4*)&S[(size_t)(e0 + row) * STAR_ + (kq - 32) * 4];
        }
        int k = kq * 4;
        sMT[(k + 0) * 72 + row] = v.x;
        sMT[(k + 1) * 72 + row] = v.y;
        sMT[(k + 2) * 72 + row] = v.z;
        sMT[(k + 3) * 72 + row] = v.w;
    }
    #pragma unroll
    for (int it = 0; it < 24; it++) {
        int idx = tx + it * 256;
        int k  = idx >> 5;
        int cq = idx & 31;
        *(float4*)&sW[k * 132 + cq * 4] = *(const float4*)&Wt[k * OUTC + cq * 4];
    }
    __syncthreads();

    const int c0 = (tx & 31) * 4;
    const int r0 = (tx >> 5) * 8;

    float4 acc[8];
    #pragma unroll
    for (int i = 0; i < 8; i++) acc[i] = make_float4(0.f, 0.f, 0.f, 0.f);

    #pragma unroll 4
    for (int k = 0; k < KTOT; k++) {
        float4 w4 = *(float4*)&sW[k * 132 + c0];
        float4 xa = *(float4*)&sMT[k * 72 + r0];
        float4 xb = *(float4*)&sMT[k * 72 + r0 + 4];
        float xs[8] = {xa.x, xa.y, xa.z, xa.w, xb.x, xb.y, xb.z, xb.w};
        #pragma unroll
        for (int i = 0; i < 8; i++) {
            float x = xs[i];
            acc[i].x += x * w4.x; acc[i].y += x * w4.y; acc[i].z += x * w4.z; acc[i].w += x * w4.w;
        }
    }

    float4 bt4 = *(const float4*)&bt[c0];
    #pragma unroll
    for (int i = 0; i < 8; i++) {
        int e = e0 + r0 + i;
        float4 o = make_float4(acc[i].x + bt4.x, acc[i].y + bt4.y, acc[i].z + bt4.z, acc[i].w + bt4.w);
        *(float4*)&g_Y[(size_t)e * OUTC + c0] = o;
    }
}

// ---------------- node aggregation + finalize: out += elu( mean_e Y[e] ) ----------------
// warp per node; 12500 blocks * 8 warps = 100000 exact
__global__ __launch_bounds__(256) void node_agg_kernel(float* __restrict__ out)
{
    const int n = blockIdx.x * 8 + (threadIdx.x >> 5);
    const int lane = threadIdx.x & 31;
    const int base = g_baseV[n];
    const int deg  = g_histV[n];
    float4 acc = make_float4(0.f, 0.f, 0.f, 0.f);
    for (int j = 0; j < deg; j++) {
        int e = __ldg(&g_csrV_e[base + j]);           // warp-broadcast
        float4 y = *(const float4*)&g_Y[(size_t)e * OUTC + lane * 4];
        acc.x += y.x; acc.y += y.y; acc.z += y.z; acc.w += y.w;
    }
    float inv = 1.f / fmaxf((float)deg, 1.f);
    size_t o_idx = (size_t)n * OUTC + lane * 4;
    float4 o = *(const float4*)&out[o_idx];           // holds X_init
    o.x += elu1(acc.x * inv); o.y += elu1(acc.y * inv);
    o.z += elu1(acc.z * inv); o.w += elu1(acc.w * inv);
    *(float4*)&out[o_idx] = o;
}

// ---------------- launch ----------------
extern "C" void kernel_launch(void* const* d_in, const int* in_sizes, int n_in,
                              void* d_out, int out_size)
{
    const float* X  = (const float*)d_in[0];
    const int*   V  = (const int*)d_in[1];
    const int*   E  = (const int*)d_in[2];
    const float* S  = (const float*)d_in[3];
    const float* Wx = (const float*)d_in[4];
    const float* bx = (const float*)d_in[5];
    const float* Wv = (const float*)d_in[6];
    const float* bv = (const float*)d_in[7];
    const float* a  = (const float*)d_in[8];
    const float* Wt = (const float*)d_in[9];
    const float* bt = (const float*)d_in[10];
    float* out = (float*)d_out;

    void *p_histE, *p_histV, *p_ctr, *p_baseE, *p_curE, *p_baseV, *p_curV;
    cudaGetSymbolAddress(&p_histE, g_histE);
    cudaGetSymbolAddress(&p_histV, g_histV);
    cudaGetSymbolAddress(&p_ctr,   g_alloc_ctr);
    cudaGetSymbolAddress(&p_baseE, g_baseE);
    cudaGetSymbolAddress(&p_curE,  g_curE);
    cudaGetSymbolAddress(&p_baseV, g_baseV);
    cudaGetSymbolAddress(&p_curV,  g_curV);
    cudaMemsetAsync(p_histE, 0, N_EDGES * sizeof(int));
    cudaMemsetAsync(p_histV, 0, N_NODES * sizeof(int));
    cudaMemsetAsync(p_ctr,   0, 2 * sizeof(int));

    const int smem1 = (128 * 72 + 2 * 128 * 132) * (int)sizeof(float);  // 172032
    const int smem2 = (192 * 72 + 192 * 132) * (int)sizeof(float);      // 156672
    cudaFuncSetAttribute(gemm_x_kernel, cudaFuncAttributeMaxDynamicSharedMemorySize, smem1);
    cudaFuncSetAttribute(gemm2_kernel,  cudaFuncAttributeMaxDynamicSharedMemorySize, smem2);

    hist_kernel<<<6250, 256>>>(V, E);
    gemm_x_kernel<<<1563, 256, smem1>>>(X, Wx, bx, Wv, bv, a, out);
    alloc_kernel<<<782, 256>>>((const int*)p_histE, (int*)p_baseE, (int*)p_curE, N_EDGES, 0);
    alloc_kernel<<<391, 256>>>((const int*)p_histV, (int*)p_baseV, (int*)p_curV, N_NODES, 1);
    scatter_kernel<<<6250, 256>>>(V, E);
    edge_agg_kernel<<<25000, 256>>>();
    gemm2_kernel<<<3125, 256, smem2>>>(S, Wt, bt);
    node_agg_kernel<<<12500, 256>>>(out);
}

// round 5
// speedup vs baseline: 1.5382x; 1.0804x over previous
#include <cuda_runtime.h>
#include <math.h>

#define N_NODES 100000
#define N_EDGES 200000
#define NNZ_    1600000
#define INC 128
#define OUTC 128
#define STAR_ 64
#define KTOT 192

// ---------------- device scratch (allocation-free) ----------------
__device__ float g_Xfeat[(size_t)N_NODES * OUTC];   // 51.2 MB
__device__ float g_scores[N_NODES];
__device__ float g_Yv2e[(size_t)N_EDGES * OUTC];    // 102.4 MB (elu'd rows)
__device__ float g_Magg[(size_t)N_NODES * KTOT];    // 76.8 MB (mean message per node)

// CSR by edge (segments of nnz grouped by E), payload = V
__device__ int g_histE[N_EDGES];
__device__ int g_baseE[N_EDGES];
__device__ int g_curE[N_EDGES];
__device__ int g_csrE_v[NNZ_];
// CSR by node (segments of nnz grouped by V), payload = E
__device__ int g_histV[N_NODES];
__device__ int g_baseV[N_NODES];
__device__ int g_curV[N_NODES];
__device__ int g_csrV_e[NNZ_];
__device__ int g_alloc_ctr[2];

// ---------------- helpers ----------------
__device__ __forceinline__ float elu1(float x) {
    return x > 0.f ? x : expm1f(x);
}

// ---------------- Kernel 1: X_init = X@Wx+bx ; X_feat = X@Wv+bv ; scores = X_feat@a ----------------
__global__ __launch_bounds__(256, 1) void gemm_x_kernel(
    const float* __restrict__ X, const float* __restrict__ Wx, const float* __restrict__ bx,
    const float* __restrict__ Wv, const float* __restrict__ bv, const float* __restrict__ a_vec,
    float* __restrict__ Xinit)
{
    extern __shared__ float sm[];
    float* sXT = sm;                 // 128*72
    float* sWx = sm + 128 * 72;      // 128*132
    float* sWv = sWx + 128 * 132;    // 128*132

    const int tx = threadIdx.x;
    const int n0 = blockIdx.x * 64;

    #pragma unroll
    for (int it = 0; it < 8; it++) {
        int idx = tx + it * 256;
        int row = idx >> 5;
        int kq  = idx & 31;
        int n = n0 + row;
        float4 v = make_float4(0.f, 0.f, 0.f, 0.f);
        if (n < N_NODES) v = *(const float4*)&X[(size_t)n * INC + kq * 4];
        sXT[(kq * 4 + 0) * 72 + row] = v.x;
        sXT[(kq * 4 + 1) * 72 + row] = v.y;
        sXT[(kq * 4 + 2) * 72 + row] = v.z;
        sXT[(kq * 4 + 3) * 72 + row] = v.w;
    }
    #pragma unroll
    for (int it = 0; it < 16; it++) {
        int idx = tx + it * 256;
        int k  = idx >> 5;
        int cq = idx & 31;
        *(float4*)&sWx[k * 132 + cq * 4] = *(const float4*)&Wx[k * OUTC + cq * 4];
        *(float4*)&sWv[k * 132 + cq * 4] = *(const float4*)&Wv[k * OUTC + cq * 4];
    }
    __syncthreads();

    const int c0 = (tx & 31) * 4;
    const int r0 = (tx >> 5) * 8;

    float4 ax[8], av[8];
    #pragma unroll
    for (int i = 0; i < 8; i++) {
        ax[i] = make_float4(0.f, 0.f, 0.f, 0.f);
        av[i] = make_float4(0.f, 0.f, 0.f, 0.f);
    }

    #pragma unroll 4
    for (int k = 0; k < 128; k++) {
        float4 wx4 = *(float4*)&sWx[k * 132 + c0];
        float4 wv4 = *(float4*)&sWv[k * 132 + c0];
        float4 xa = *(float4*)&sXT[k * 72 + r0];
        float4 xb = *(float4*)&sXT[k * 72 + r0 + 4];
        float xs[8] = {xa.x, xa.y, xa.z, xa.w, xb.x, xb.y, xb.z, xb.w};
        #pragma unroll
        for (int i = 0; i < 8; i++) {
            float x = xs[i];
            ax[i].x += x * wx4.x; ax[i].y += x * wx4.y; ax[i].z += x * wx4.z; ax[i].w += x * wx4.w;
            av[i].x += x * wv4.x; av[i].y += x * wv4.y; av[i].z += x * wv4.z; av[i].w += x * wv4.w;
        }
    }

    float4 bx4 = *(const float4*)&bx[c0];
    float4 bv4 = *(const float4*)&bv[c0];
    float4 aa4 = *(const float4*)&a_vec[c0];
    const int lane = tx & 31;
    #pragma unroll
    for (int i = 0; i < 8; i++) {
        int n = n0 + r0 + i;
        if (n < N_NODES) {   // warp-uniform guard
            float4 o = make_float4(ax[i].x + bx4.x, ax[i].y + bx4.y, ax[i].z + bx4.z, ax[i].w + bx4.w);
            *(float4*)&Xinit[(size_t)n * OUTC + c0] = o;
            float4 f = make_float4(av[i].x + bv4.x, av[i].y + bv4.y, av[i].z + bv4.z, av[i].w + bv4.w);
            *(float4*)&g_Xfeat[(size_t)n * OUTC + c0] = f;
            float part = f.x * aa4.x + f.y * aa4.y + f.z * aa4.z + f.w * aa4.w;
            #pragma unroll
            for (int off = 16; off; off >>= 1) part += __shfl_down_sync(0xffffffffu, part, off);
            if (lane == 0) g_scores[n] = part;
        }
    }
}

// ---------------- histogram: deg per edge + deg per node ----------------
__global__ __launch_bounds__(256) void hist_kernel(const int* __restrict__ V, const int* __restrict__ E)
{
    int i = blockIdx.x * 256 + threadIdx.x;     // 6250*256 = NNZ exact
    atomicAdd(&g_histE[__ldg(&E[i])], 1);
    atomicAdd(&g_histV[__ldg(&V[i])], 1);
}

// ---------------- segment-base allocation ----------------
__global__ __launch_bounds__(256) void alloc_kernel(const int* __restrict__ hist,
        int* __restrict__ base, int* __restrict__ cur, int len, int ctr_idx)
{
    __shared__ int s_warp[8];
    __shared__ int s_base;
    const int t = threadIdx.x;
    const int i = blockIdx.x * 256 + t;
    const int lane = t & 31, wid = t >> 5;
    int v = (i < len) ? hist[i] : 0;
    int x = v;
    #pragma unroll
    for (int off = 1; off < 32; off <<= 1) {
        int y = __shfl_up_sync(0xffffffffu, x, off);
        if (lane >= off) x += y;
    }
    if (lane == 31) s_warp[wid] = x;
    __syncthreads();
    if (wid == 0) {
        int orig = (lane < 8) ? s_warp[lane] : 0;
        int s = orig;
        #pragma unroll
        for (int off = 1; off < 8; off <<= 1) {
            int y = __shfl_up_sync(0xffffffffu, s, off);
            if (lane >= off) s += y;
        }
        if (lane == 7) s_base = atomicAdd(&g_alloc_ctr[ctr_idx], s);
        if (lane < 8) s_warp[lane] = s - orig;
    }
    __syncthreads();
    if (i < len) {
        int excl = (x - v) + s_warp[wid] + s_base;
        base[i] = excl;
        cur[i]  = excl;
    }
}

// ---------------- scatter nnz into both CSRs ----------------
__global__ __launch_bounds__(256) void scatter_kernel(const int* __restrict__ V, const int* __restrict__ E)
{
    int i = blockIdx.x * 256 + threadIdx.x;     // NNZ exact
    int v = __ldg(&V[i]);
    int e = __ldg(&E[i]);
    int pE = atomicAdd(&g_curE[e], 1);
    g_csrE_v[pE] = v;
    int pV = atomicAdd(&g_curV[v], 1);
    g_csrV_e[pV] = e;
}

// ---------------- edge aggregation: Yv2e[e] = elu( sum w_i*Xfeat[v_i] / sum w_i ) ----------------
__global__ __launch_bounds__(256) void edge_agg_kernel()
{
    const int e = blockIdx.x * 8 + (threadIdx.x >> 5);   // 25000*8 = 200000
    const int lane = threadIdx.x & 31;
    const int base = g_baseE[e];
    const int deg  = g_histE[e];
    float4 acc = make_float4(0.f, 0.f, 0.f, 0.f);
    float denom = 0.f;
    for (int j = 0; j < deg; j++) {
        int v = __ldg(&g_csrE_v[base + j]);              // warp-broadcast
        float s = g_scores[v];
        s = s > 0.f ? s : 0.2f * s;
        float w = expf(s);
        denom += w;
        float4 xf = *(const float4*)&g_Xfeat[(size_t)v * OUTC + lane * 4];
        acc.x += w * xf.x; acc.y += w * xf.y; acc.z += w * xf.z; acc.w += w * xf.w;
    }
    float inv = (deg > 0) ? (1.f / denom) : 0.f;
    float4 o;
    o.x = elu1(acc.x * inv); o.y = elu1(acc.y * inv);
    o.z = elu1(acc.z * inv); o.w = elu1(acc.w * inv);
    *(float4*)&g_Yv2e[(size_t)e * OUTC + lane * 4] = o;
}

// ---------------- node aggregation: Magg[n] = mean over incident edges of [Yv2e[e], S[e]] ----------------
// warp per node; 12500 blocks * 8 warps = 100000 exact
__global__ __launch_bounds__(256) void node_agg_kernel(const float* __restrict__ S)
{
    const int n = blockIdx.x * 8 + (threadIdx.x >> 5);
    const int lane = threadIdx.x & 31;
    const int base = g_baseV[n];
    const int deg  = g_histV[n];
    float4 accY = make_float4(0.f, 0.f, 0.f, 0.f);
    float2 accS = make_float2(0.f, 0.f);
    for (int j = 0; j < deg; j++) {
        int e = __ldg(&g_csrV_e[base + j]);              // warp-broadcast
        float4 y = *(const float4*)&g_Yv2e[(size_t)e * OUTC + lane * 4];
        accY.x += y.x; accY.y += y.y; accY.z += y.z; accY.w += y.w;
        float2 s2 = *(const float2*)&S[(size_t)e * STAR_ + lane * 2];
        accS.x += s2.x; accS.y += s2.y;
    }
    float inv = 1.f / fmaxf((float)deg, 1.f);
    accY.x *= inv; accY.y *= inv; accY.z *= inv; accY.w *= inv;
    accS.x *= inv; accS.y *= inv;
    *(float4*)&g_Magg[(size_t)n * KTOT + lane * 4] = accY;
    *(float2*)&g_Magg[(size_t)n * KTOT + OUTC + lane * 2] = accS;
}

// ---------------- gemm_node: out = X_init + (deg>0 ? elu(Magg@Wt + bt) : 0) ----------------
// Block: 64 node-rows x 128 cols, K=192.
__global__ __launch_bounds__(256, 1) void gemm_node_kernel(
    const float* __restrict__ Wt, const float* __restrict__ bt, float* __restrict__ out)
{
    extern __shared__ float sm[];
    float* sMT = sm;               // 192*72
    float* sW  = sm + 192 * 72;    // 192*132

    const int tx = threadIdx.x;
    const int n0 = blockIdx.x * 64;

    #pragma unroll
    for (int it = 0; it < 12; it++) {
        int idx = tx + it * 256;       // 0..3071 = 64 rows * 48 float4
        int row = idx / 48;
        int kq  = idx % 48;
        int n = n0 + row;
        float4 v = make_float4(0.f, 0.f, 0.f, 0.f);
        if (n < N_NODES) v = *(const float4*)&g_Magg[(size_t)n * KTOT + kq * 4];
        int k = kq * 4;
        sMT[(k + 0) * 72 + row] = v.x;
        sMT[(k + 1) * 72 + row] = v.y;
        sMT[(k + 2) * 72 + row] = v.z;
        sMT[(k + 3) * 72 + row] = v.w;
    }
    #pragma unroll
    for (int it = 0; it < 24; it++) {
        int idx = tx + it * 256;       // 0..6143 = 192*32
        int k  = idx >> 5;
        int cq = idx & 31;
        *(float4*)&sW[k * 132 + cq * 4] = *(const float4*)&Wt[k * OUTC + cq * 4];
    }
    __syncthreads();

    const int c0 = (tx & 31) * 4;
    const int r0 = (tx >> 5) * 8;

    float4 acc[8];
    #pragma unroll
    for (int i = 0; i < 8; i++) acc[i] = make_float4(0.f, 0.f, 0.f, 0.f);

    #pragma unroll 4
    for (int k = 0; k < KTOT; k++) {
        float4 w4 = *(float4*)&sW[k * 132 + c0];
        float4 xa = *(float4*)&sMT[k * 72 + r0];
        float4 xb = *(float4*)&sMT[k * 72 + r0 + 4];
        float xs[8] = {xa.x, xa.y, xa.z, xa.w, xb.x, xb.y, xb.z, xb.w};
        #pragma unroll
        for (int i = 0; i < 8; i++) {
            float x = xs[i];
            acc[i].x += x * w4.x; acc[i].y += x * w4.y; acc[i].z += x * w4.z; acc[i].w += x * w4.w;
        }
    }

    float4 bt4 = *(const float4*)&bt[c0];
    #pragma unroll
    for (int i = 0; i < 8; i++) {
        int n = n0 + r0 + i;
        if (n < N_NODES) {
            size_t oidx = (size_t)n * OUTC + c0;
            float4 o = *(const float4*)&out[oidx];           // X_init
            if (g_histV[n] > 0) {                            // isolated node -> elu(0)=0
                o.x += elu1(acc[i].x + bt4.x);
                o.y += elu1(acc[i].y + bt4.y);
                o.z += elu1(acc[i].z + bt4.z);
                o.w += elu1(acc[i].w + bt4.w);
            }
            *(float4*)&out[oidx] = o;
        }
    }
}

// ---------------- launch ----------------
extern "C" void kernel_launch(void* const* d_in, const int* in_sizes, int n_in,
                              void* d_out, int out_size)
{
    const float* X  = (const float*)d_in[0];
    const int*   V  = (const int*)d_in[1];
    const int*   E  = (const int*)d_in[2];
    const float* S  = (const float*)d_in[3];
    const float* Wx = (const float*)d_in[4];
    const float* bx = (const float*)d_in[5];
    const float* Wv = (const float*)d_in[6];
    const float* bv = (const float*)d_in[7];
    const float* a  = (const float*)d_in[8];
    const float* Wt = (const float*)d_in[9];
    const float* bt = (const float*)d_in[10];
    float* out = (float*)d_out;

    void *p_histE, *p_histV, *p_ctr, *p_baseE, *p_curE, *p_baseV, *p_curV;
    cudaGetSymbolAddress(&p_histE, g_histE);
    cudaGetSymbolAddress(&p_histV, g_histV);
    cudaGetSymbolAddress(&p_ctr,   g_alloc_ctr);
    cudaGetSymbolAddress(&p_baseE, g_baseE);
    cudaGetSymbolAddress(&p_curE,  g_curE);
    cudaGetSymbolAddress(&p_baseV, g_baseV);
    cudaGetSymbolAddress(&p_curV,  g_curV);
    cudaMemsetAsync(p_histE, 0, N_EDGES * sizeof(int));
    cudaMemsetAsync(p_histV, 0, N_NODES * sizeof(int));
    cudaMemsetAsync(p_ctr,   0, 2 * sizeof(int));

    const int smem1 = (128 * 72 + 2 * 128 * 132) * (int)sizeof(float);  // 172032
    const int smem2 = (192 * 72 + 192 * 132) * (int)sizeof(float);      // 156672
    cudaFuncSetAttribute(gemm_x_kernel,    cudaFuncAttributeMaxDynamicSharedMemorySize, smem1);
    cudaFuncSetAttribute(gemm_node_kernel, cudaFuncAttributeMaxDynamicSharedMemorySize, smem2);

    hist_kernel<<<6250, 256>>>(V, E);
    gemm_x_kernel<<<1563, 256, smem1>>>(X, Wx, bx, Wv, bv, a, out);
    alloc_kernel<<<782, 256>>>((const int*)p_histE, (int*)p_baseE, (int*)p_curE, N_EDGES, 0);
    alloc_kernel<<<391, 256>>>((const int*)p_histV, (int*)p_baseV, (int*)p_curV, N_NODES, 1);
    scatter_kernel<<<6250, 256>>>(V, E);
    edge_agg_kernel<<<25000, 256>>>();
    node_agg_kernel<<<12500, 256>>>(S);
    gemm_node_kernel<<<1563, 256, smem2>>>(Wt, bt, out);
}

// round 8
// speedup vs baseline: 1.5877x; 1.0322x over previous
#include <cuda_runtime.h>
#include <math.h>
#include <stdint.h>

#define N_NODES 100000
#define N_EDGES 200000
#define NNZ_    1600000
#define INC 128
#define OUTC 128
#define STAR_ 64
#define KTOT 192

typedef unsigned long long u64;

// ---------------- device scratch (allocation-free) ----------------
__device__ float g_Xfeat[(size_t)N_NODES * OUTC];   // 51.2 MB
__device__ float g_scores[N_NODES];
__device__ float g_Yv2e[(size_t)N_EDGES * OUTC];    // 102.4 MB (elu'd rows)
__device__ float g_Magg[(size_t)N_NODES * KTOT];    // 76.8 MB (mean message per node)

// CSR by edge (payload = V) / by node (payload = E)
__device__ int g_histE[N_EDGES];
__device__ int g_baseE[N_EDGES];
__device__ int g_curE[N_EDGES];
__device__ int g_csrE_v[NNZ_];
__device__ int g_histV[N_NODES];
__device__ int g_baseV[N_NODES];
__device__ int g_curV[N_NODES];
__device__ int g_csrV_e[NNZ_];
__device__ int g_alloc_ctr[2];

// ---------------- helpers ----------------
__device__ __forceinline__ float elu1(float x) {
    return x > 0.f ? x : expm1f(x);
}
// packed f32x2 FMA (Blackwell FFMA2 — only reachable via PTX, ptxas won't auto-fuse)
__device__ __forceinline__ u64 pack2(float v) {
    u64 r; asm("mov.b64 %0, {%1, %1};" : "=l"(r) : "f"(v)); return r;
}
__device__ __forceinline__ void fma2(u64& d, u64 a, u64 b) {
    asm("fma.rn.f32x2 %0, %1, %2, %0;" : "+l"(d) : "l"(a), "l"(b));
}
__device__ __forceinline__ float2 unpack2(u64 v) {
    float2 r; asm("mov.b64 {%0, %1}, %2;" : "=f"(r.x), "=f"(r.y) : "l"(v)); return r;
}

// ---------------- Kernel 1: X_init = X@Wx+bx ; X_feat = X@Wv+bv ; scores = X_feat@a ----------------
__global__ __launch_bounds__(256, 1) void gemm_x_kernel(
    const float* __restrict__ X, const float* __restrict__ Wx, const float* __restrict__ bx,
    const float* __restrict__ Wv, const float* __restrict__ bv, const float* __restrict__ a_vec,
    float* __restrict__ Xinit)
{
    extern __shared__ float sm[];
    float* sXT = sm;                 // 128*72
    float* sWx = sm + 128 * 72;      // 128*132  (132*4B = 33*16B -> float4/u64x2 aligned per row)
    float* sWv = sWx + 128 * 132;    // 128*132

    const int tx = threadIdx.x;
    const int n0 = blockIdx.x * 64;

    #pragma unroll
    for (int it = 0; it < 8; it++) {
        int idx = tx + it * 256;
        int row = idx >> 5;
        int kq  = idx & 31;
        int n = n0 + row;
        float4 v = make_float4(0.f, 0.f, 0.f, 0.f);
        if (n < N_NODES) v = *(const float4*)&X[(size_t)n * INC + kq * 4];
        sXT[(kq * 4 + 0) * 72 + row] = v.x;
        sXT[(kq * 4 + 1) * 72 + row] = v.y;
        sXT[(kq * 4 + 2) * 72 + row] = v.z;
        sXT[(kq * 4 + 3) * 72 + row] = v.w;
    }
    #pragma unroll
    for (int it = 0; it < 16; it++) {
        int idx = tx + it * 256;
        int k  = idx >> 5;
        int cq = idx & 31;
        *(float4*)&sWx[k * 132 + cq * 4] = *(const float4*)&Wx[k * OUTC + cq * 4];
        *(float4*)&sWv[k * 132 + cq * 4] = *(const float4*)&Wv[k * OUTC + cq * 4];
    }
    __syncthreads();

    const int c0 = (tx & 31) * 4;
    const int r0 = (tx >> 5) * 8;

    // packed accumulators: [row][col-pair]
    u64 ax0[8], ax1[8], av0[8], av1[8];
    #pragma unroll
    for (int i = 0; i < 8; i++) { ax0[i] = 0ull; ax1[i] = 0ull; av0[i] = 0ull; av1[i] = 0ull; }

    #pragma unroll 4
    for (int k = 0; k < 128; k++) {
        ulonglong2 wx = *(ulonglong2*)&sWx[k * 132 + c0];
        ulonglong2 wv = *(ulonglong2*)&sWv[k * 132 + c0];
        float4 xa = *(float4*)&sXT[k * 72 + r0];
        float4 xb = *(float4*)&sXT[k * 72 + r0 + 4];
        float xs[8] = {xa.x, xa.y, xa.z, xa.w, xb.x, xb.y, xb.z, xb.w};
        #pragma unroll
        for (int i = 0; i < 8; i++) {
            u64 xx = pack2(xs[i]);
            fma2(ax0[i], xx, wx.x); fma2(ax1[i], xx, wx.y);
            fma2(av0[i], xx, wv.x); fma2(av1[i], xx, wv.y);
        }
    }

    float4 bx4 = *(const float4*)&bx[c0];
    float4 bv4 = *(const float4*)&bv[c0];
    float4 aa4 = *(const float4*)&a_vec[c0];
    const int lane = tx & 31;
    #pragma unroll
    for (int i = 0; i < 8; i++) {
        int n = n0 + r0 + i;
        if (n < N_NODES) {   // warp-uniform guard
            float2 x01 = unpack2(ax0[i]), x23 = unpack2(ax1[i]);
            float4 o = make_float4(x01.x + bx4.x, x01.y + bx4.y, x23.x + bx4.z, x23.y + bx4.w);
            *(float4*)&Xinit[(size_t)n * OUTC + c0] = o;
            float2 v01 = unpack2(av0[i]), v23 = unpack2(av1[i]);
            float4 f = make_float4(v01.x + bv4.x, v01.y + bv4.y, v23.x + bv4.z, v23.y + bv4.w);
            *(float4*)&g_Xfeat[(size_t)n * OUTC + c0] = f;
            float part = f.x * aa4.x + f.y * aa4.y + f.z * aa4.z + f.w * aa4.w;
            #pragma unroll
            for (int off = 16; off; off >>= 1) part += __shfl_down_sync(0xffffffffu, part, off);
            if (lane == 0) g_scores[n] = part;
        }
    }
}

// ---------------- histogram: deg per edge + deg per node ----------------
__global__ __launch_bounds__(256) void hist_kernel(const int* __restrict__ V, const int* __restrict__ E)
{
    int i = blockIdx.x * 256 + threadIdx.x;     // 6250*256 = NNZ exact
    atomicAdd(&g_histE[__ldg(&E[i])], 1);
    atomicAdd(&g_histV[__ldg(&V[i])], 1);
}

// ---------------- segment-base allocation ----------------
__global__ __launch_bounds__(256) void alloc_kernel(const int* __restrict__ hist,
        int* __restrict__ base, int* __restrict__ cur, int len, int ctr_idx)
{
    __shared__ int s_warp[8];
    __shared__ int s_base;
    const int t = threadIdx.x;
    const int i = blockIdx.x * 256 + t;
    const int lane = t & 31, wid = t >> 5;
    int v = (i < len) ? hist[i] : 0;
    int x = v;
    #pragma unroll
    for (int off = 1; off < 32; off <<= 1) {
        int y = __shfl_up_sync(0xffffffffu, x, off);
        if (lane >= off) x += y;
    }
    if (lane == 31) s_warp[wid] = x;
    __syncthreads();
    if (wid == 0) {
        int orig = (lane < 8) ? s_warp[lane] : 0;
        int s = orig;
        #pragma unroll
        for (int off = 1; off < 8; off <<= 1) {
            int y = __shfl_up_sync(0xffffffffu, s, off);
            if (lane >= off) s += y;
        }
        if (lane == 7) s_base = atomicAdd(&g_alloc_ctr[ctr_idx], s);
        if (lane < 8) s_warp[lane] = s - orig;
    }
    __syncthreads();
    if (i < len) {
        int excl = (x - v) + s_warp[wid] + s_base;
        base[i] = excl;
        cur[i]  = excl;
    }
}

// ---------------- scatter nnz into both CSRs ----------------
__global__ __launch_bounds__(256) void scatter_kernel(const int* __restrict__ V, const int* __restrict__ E)
{
    int i = blockIdx.x * 256 + threadIdx.x;     // NNZ exact
    int v = __ldg(&V[i]);
    int e = __ldg(&E[i]);
    int pE = atomicAdd(&g_curE[e], 1);
    g_csrE_v[pE] = v;
    int pV = atomicAdd(&g_curV[v], 1);
    g_csrV_e[pV] = e;
}

// ---------------- edge aggregation: Yv2e[e] = elu( sum w_i*Xfeat[v_i] / sum w_i ) ----------------
__global__ __launch_bounds__(256) void edge_agg_kernel()
{
    const int e = blockIdx.x * 8 + (threadIdx.x >> 5);   // 25000*8 = 200000
    const int lane = threadIdx.x & 31;
    const int base = g_baseE[e];
    const int deg  = g_histE[e];
    float4 acc = make_float4(0.f, 0.f, 0.f, 0.f);
    float denom = 0.f;
    for (int j = 0; j < deg; j++) {
        int v = __ldg(&g_csrE_v[base + j]);              // warp-broadcast
        float s = g_scores[v];
        s = s > 0.f ? s : 0.2f * s;
        float w = expf(s);
        denom += w;
        float4 xf = *(const float4*)&g_Xfeat[(size_t)v * OUTC + lane * 4];
        acc.x += w * xf.x; acc.y += w * xf.y; acc.z += w * xf.z; acc.w += w * xf.w;
    }
    float inv = (deg > 0) ? (1.f / denom) : 0.f;
    float4 o;
    o.x = elu1(acc.x * inv); o.y = elu1(acc.y * inv);
    o.z = elu1(acc.z * inv); o.w = elu1(acc.w * inv);
    *(float4*)&g_Yv2e[(size_t)e * OUTC + lane * 4] = o;
}

// ---------------- node aggregation: Magg[n] = mean over incident edges of [Yv2e[e], S[e]] ----------------
__global__ __launch_bounds__(256) void node_agg_kernel(const float* __restrict__ S)
{
    const int n = blockIdx.x * 8 + (threadIdx.x >> 5);   // 12500*8 = 100000
    const int lane = threadIdx.x & 31;
    const int base = g_baseV[n];
    const int deg  = g_histV[n];
    float4 accY = make_float4(0.f, 0.f, 0.f, 0.f);
    float2 accS = make_float2(0.f, 0.f);
    for (int j = 0; j < deg; j++) {
        int e = __ldg(&g_csrV_e[base + j]);              // warp-broadcast
        float4 y = *(const float4*)&g_Yv2e[(size_t)e * OUTC + lane * 4];
        accY.x += y.x; accY.y += y.y; accY.z += y.z; accY.w += y.w;
        float2 s2 = *(const float2*)&S[(size_t)e * STAR_ + lane * 2];
        accS.x += s2.x; accS.y += s2.y;
    }
    float inv = 1.f / fmaxf((float)deg, 1.f);
    accY.x *= inv; accY.y *= inv; accY.z *= inv; accY.w *= inv;
    accS.x *= inv; accS.y *= inv;
    *(float4*)&g_Magg[(size_t)n * KTOT + lane * 4] = accY;
    *(float2*)&g_Magg[(size_t)n * KTOT + OUTC + lane * 2] = accS;
}

// ---------------- gemm_node: out = X_init + (deg>0 ? elu(Magg@Wt + bt) : 0) ----------------
__global__ __launch_bounds__(256, 1) void gemm_node_kernel(
    const float* __restrict__ Wt, const float* __restrict__ bt, float* __restrict__ out)
{
    extern __shared__ float sm[];
    float* sMT = sm;               // 192*72
    float* sW  = sm + 192 * 72;    // 192*132

    const int tx = threadIdx.x;
    const int n0 = blockIdx.x * 64;

    #pragma unroll
    for (int it = 0; it < 12; it++) {
        int idx = tx + it * 256;       // 0..3071 = 64 rows * 48 float4
        int row = idx / 48;
        int kq  = idx % 48;
        int n = n0 + row;
        float4 v = make_float4(0.f, 0.f, 0.f, 0.f);
        if (n < N_NODES) v = *(const float4*)&g_Magg[(size_t)n * KTOT + kq * 4];
        int k = kq * 4;
        sMT[(k + 0) * 72 + row] = v.x;
        sMT[(k + 1) * 72 + row] = v.y;
        sMT[(k + 2) * 72 + row] = v.z;
        sMT[(k + 3) * 72 + row] = v.w;
    }
    #pragma unroll
    for (int it = 0; it < 24; it++) {
        int idx = tx + it * 256;       // 0..6143 = 192*32
        int k  = idx >> 5;
        int cq = idx & 31;
        *(float4*)&sW[k * 132 + cq * 4] = *(const float4*)&Wt[k * OUTC + cq * 4];
    }
    __syncthreads();

    const int c0 = (tx & 31) * 4;
    const int r0 = (tx >> 5) * 8;

    u64 a0[8], a1[8];
    #pragma unroll
    for (int i = 0; i < 8; i++) { a0[i] = 0ull; a1[i] = 0ull; }

    #pragma unroll 4
    for (int k = 0; k < KTOT; k++) {
        ulonglong2 w2 = *(ulonglong2*)&sW[k * 132 + c0];
        float4 xa = *(float4*)&sMT[k * 72 + r0];
        float4 xb = *(float4*)&sMT[k * 72 + r0 + 4];
        float xs[8] = {xa.x, xa.y, xa.z, xa.w, xb.x, xb.y, xb.z, xb.w};
        #pragma unroll
        for (int i = 0; i < 8; i++) {
            u64 xx = pack2(xs[i]);
            fma2(a0[i], xx, w2.x); fma2(a1[i], xx, w2.y);
        }
    }

    float4 bt4 = *(const float4*)&bt[c0];
    #pragma unroll
    for (int i = 0; i < 8; i++) {
        int n = n0 + r0 + i;
        if (n < N_NODES) {
            size_t oidx = (size_t)n * OUTC + c0;
            float4 o = *(const float4*)&out[oidx];           // X_init
            if (g_histV[n] > 0) {                            // isolated node -> elu(0)=0
                float2 p01 = unpack2(a0[i]), p23 = unpack2(a1[i]);
                o.x += elu1(p01.x + bt4.x);
                o.y += elu1(p01.y + bt4.y);
                o.z += elu1(p23.x + bt4.z);
                o.w += elu1(p23.y + bt4.w);
            }
            *(float4*)&out[oidx] = o;
        }
    }
}

// ---------------- launch ----------------
extern "C" void kernel_launch(void* const* d_in, const int* in_sizes, int n_in,
                              void* d_out, int out_size)
{
    const float* X  = (const float*)d_in[0];
    const int*   V  = (const int*)d_in[1];
    const int*   E  = (const int*)d_in[2];
    const float* S  = (const float*)d_in[3];
    const float* Wx = (const float*)d_in[4];
    const float* bx = (const float*)d_in[5];
    const float* Wv = (const float*)d_in[6];
    const float* bv = (const float*)d_in[7];
    const float* a  = (const float*)d_in[8];
    const float* Wt = (const float*)d_in[9];
    const float* bt = (const float*)d_in[10];
    float* out = (float*)d_out;

    void *p_histE, *p_histV, *p_ctr, *p_baseE, *p_curE, *p_baseV, *p_curV;
    cudaGetSymbolAddress(&p_histE, g_histE);
    cudaGetSymbolAddress(&p_histV, g_histV);
    cudaGetSymbolAddress(&p_ctr,   g_alloc_ctr);
    cudaGetSymbolAddress(&p_baseE, g_baseE);
    cudaGetSymbolAddress(&p_curE,  g_curE);
    cudaGetSymbolAddress(&p_baseV, g_baseV);
    cudaGetSymbolAddress(&p_curV,  g_curV);
    cudaMemsetAsync(p_histE, 0, N_EDGES * sizeof(int));
    cudaMemsetAsync(p_histV, 0, N_NODES * sizeof(int));
    cudaMemsetAsync(p_ctr,   0, 2 * sizeof(int));

    const int smem1 = (128 * 72 + 2 * 128 * 132) * (int)sizeof(float);  // 172032
    const int smem2 = (192 * 72 + 192 * 132) * (int)sizeof(float);      // 156672
    cudaFuncSetAttribute(gemm_x_kernel,    cudaFuncAttributeMaxDynamicSharedMemorySize, smem1);
    cudaFuncSetAttribute(gemm_node_kernel, cudaFuncAttributeMaxDynamicSharedMemorySize, smem2);

    hist_kernel<<<6250, 256>>>(V, E);
    gemm_x_kernel<<<1563, 256, smem1>>>(X, Wx, bx, Wv, bv, a, out);
    alloc_kernel<<<782, 256>>>((const int*)p_histE, (int*)p_baseE, (int*)p_curE, N_EDGES, 0);
    alloc_kernel<<<391, 256>>>((const int*)p_histV, (int*)p_baseV, (int*)p_curV, N_NODES, 1);
    scatter_kernel<<<6250, 256>>>(V, E);
    edge_agg_kernel<<<25000, 256>>>();
    node_agg_kernel<<<12500, 256>>>(S);
    gemm_node_kernel<<<1563, 256, smem2>>>(Wt, bt, out);
}

// round 9
// speedup vs baseline: 1.7434x; 1.0980x over previous
#include <cuda_runtime.h>
#include <math.h>
#include <stdint.h>

#define N_NODES 100000
#define N_EDGES 200000
#define NNZ_    1600000
#define INC 128
#define OUTC 128
#define STAR_ 64
#define KTOT 192

typedef unsigned long long u64;

// ---------------- device scratch (allocation-free) ----------------
__device__ float g_Xfeat[(size_t)N_NODES * OUTC];   // 51.2 MB
__device__ float g_scores[N_NODES];
__device__ float g_Yv2e[(size_t)N_EDGES * OUTC];    // 102.4 MB (elu'd rows)
__device__ float g_Magg[(size_t)N_NODES * KTOT];    // 76.8 MB (mean message per node)

// CSR by edge (payload = V) / by node (payload = E)
__device__ int g_histE[N_EDGES];
__device__ int g_baseE[N_EDGES];
__device__ int g_curE[N_EDGES];
__device__ int g_csrE_v[NNZ_];
__device__ int g_histV[N_NODES];
__device__ int g_baseV[N_NODES];
__device__ int g_curV[N_NODES];
__device__ int g_csrV_e[NNZ_];
__device__ int g_alloc_ctr[2];

// ---------------- helpers ----------------
__device__ __forceinline__ float elu1(float x) {
    return x > 0.f ? x : expm1f(x);
}
// packed f32x2 FMA (Blackwell FFMA2 path via PTX)
__device__ __forceinline__ u64 pack2(float v) {
    u64 r; asm("mov.b64 %0, {%1, %1};" : "=l"(r) : "f"(v)); return r;
}
__device__ __forceinline__ void fma2(u64& d, u64 a, u64 b) {
    asm("fma.rn.f32x2 %0, %1, %2, %0;" : "+l"(d) : "l"(a), "l"(b));
}
__device__ __forceinline__ float2 unpack2(u64 v) {
    float2 r; asm("mov.b64 {%0, %1}, %2;" : "=f"(r.x), "=f"(r.y) : "l"(v)); return r;
}

// ---------------- Kernel 1: X_init = X@Wx+bx ; X_feat = X@Wv+bv ; scores = X_feat@a ----------------
// 64 rows x 128 cols per block; W staged in 2 k-chunks of 64 -> 102 KB smem -> 2 CTAs/SM.
__global__ __launch_bounds__(256, 2) void gemm_x_kernel(
    const float* __restrict__ X, const float* __restrict__ Wx, const float* __restrict__ bx,
    const float* __restrict__ Wv, const float* __restrict__ bv, const float* __restrict__ a_vec,
    float* __restrict__ Xinit)
{
    extern __shared__ float sm[];
    float* sXT = sm;                 // 128*72  (k-major, transposed X tile)
    float* sWx = sm + 128 * 72;      // 64*132  (one k-chunk)
    float* sWv = sWx + 64 * 132;     // 64*132

    const int tx = threadIdx.x;
    const int n0 = blockIdx.x * 64;

    #pragma unroll
    for (int it = 0; it < 8; it++) {
        int idx = tx + it * 256;
        int row = idx >> 5;
        int kq  = idx & 31;
        int n = n0 + row;
        float4 v = make_float4(0.f, 0.f, 0.f, 0.f);
        if (n < N_NODES) v = *(const float4*)&X[(size_t)n * INC + kq * 4];
        sXT[(kq * 4 + 0) * 72 + row] = v.x;
        sXT[(kq * 4 + 1) * 72 + row] = v.y;
        sXT[(kq * 4 + 2) * 72 + row] = v.z;
        sXT[(kq * 4 + 3) * 72 + row] = v.w;
    }

    const int c0 = (tx & 31) * 4;
    const int r0 = (tx >> 5) * 8;

    u64 ax0[8], ax1[8], av0[8], av1[8];
    #pragma unroll
    for (int i = 0; i < 8; i++) { ax0[i] = 0ull; ax1[i] = 0ull; av0[i] = 0ull; av1[i] = 0ull; }

    #pragma unroll
    for (int c = 0; c < 2; c++) {
        // stage one 64-row k-chunk of both weight matrices
        #pragma unroll
        for (int it = 0; it < 8; it++) {
            int idx = tx + it * 256;          // 0..2047 = 64 rows * 32 float4
            int k  = idx >> 5;
            int cq = idx & 31;
            *(float4*)&sWx[k * 132 + cq * 4] = *(const float4*)&Wx[(c * 64 + k) * OUTC + cq * 4];
            *(float4*)&sWv[k * 132 + cq * 4] = *(const float4*)&Wv[(c * 64 + k) * OUTC + cq * 4];
        }
        __syncthreads();

        #pragma unroll 4
        for (int kk = 0; kk < 64; kk++) {
            int k = c * 64 + kk;
            ulonglong2 wx = *(ulonglong2*)&sWx[kk * 132 + c0];
            ulonglong2 wv = *(ulonglong2*)&sWv[kk * 132 + c0];
            float4 xa = *(float4*)&sXT[k * 72 + r0];
            float4 xb = *(float4*)&sXT[k * 72 + r0 + 4];
            float xs[8] = {xa.x, xa.y, xa.z, xa.w, xb.x, xb.y, xb.z, xb.w};
            #pragma unroll
            for (int i = 0; i < 8; i++) {
                u64 xx = pack2(xs[i]);
                fma2(ax0[i], xx, wx.x); fma2(ax1[i], xx, wx.y);
                fma2(av0[i], xx, wv.x); fma2(av1[i], xx, wv.y);
            }
        }
        __syncthreads();
    }

    float4 bx4 = *(const float4*)&bx[c0];
    float4 bv4 = *(const float4*)&bv[c0];
    float4 aa4 = *(const float4*)&a_vec[c0];
    const int lane = tx & 31;
    #pragma unroll
    for (int i = 0; i < 8; i++) {
        int n = n0 + r0 + i;
        if (n < N_NODES) {   // warp-uniform guard
            float2 x01 = unpack2(ax0[i]), x23 = unpack2(ax1[i]);
            float4 o = make_float4(x01.x + bx4.x, x01.y + bx4.y, x23.x + bx4.z, x23.y + bx4.w);
            *(float4*)&Xinit[(size_t)n * OUTC + c0] = o;
            float2 v01 = unpack2(av0[i]), v23 = unpack2(av1[i]);
            float4 f = make_float4(v01.x + bv4.x, v01.y + bv4.y, v23.x + bv4.z, v23.y + bv4.w);
            *(float4*)&g_Xfeat[(size_t)n * OUTC + c0] = f;
            float part = f.x * aa4.x + f.y * aa4.y + f.z * aa4.z + f.w * aa4.w;
            #pragma unroll
            for (int off = 16; off; off >>= 1) part += __shfl_down_sync(0xffffffffu, part, off);
            if (lane == 0) g_scores[n] = part;
        }
    }
}

// ---------------- histogram: deg per edge + deg per node ----------------
__global__ __launch_bounds__(256) void hist_kernel(const int* __restrict__ V, const int* __restrict__ E)
{
    int i = blockIdx.x * 256 + threadIdx.x;     // 6250*256 = NNZ exact
    atomicAdd(&g_histE[__ldg(&E[i])], 1);
    atomicAdd(&g_histV[__ldg(&V[i])], 1);
}

// ---------------- segment-base allocation ----------------
__global__ __launch_bounds__(256) void alloc_kernel(const int* __restrict__ hist,
        int* __restrict__ base, int* __restrict__ cur, int len, int ctr_idx)
{
    __shared__ int s_warp[8];
    __shared__ int s_base;
    const int t = threadIdx.x;
    const int i = blockIdx.x * 256 + t;
    const int lane = t & 31, wid = t >> 5;
    int v = (i < len) ? hist[i] : 0;
    int x = v;
    #pragma unroll
    for (int off = 1; off < 32; off <<= 1) {
        int y = __shfl_up_sync(0xffffffffu, x, off);
        if (lane >= off) x += y;
    }
    if (lane == 31) s_warp[wid] = x;
    __syncthreads();
    if (wid == 0) {
        int orig = (lane < 8) ? s_warp[lane] : 0;
        int s = orig;
        #pragma unroll
        for (int off = 1; off < 8; off <<= 1) {
            int y = __shfl_up_sync(0xffffffffu, s, off);
            if (lane >= off) s += y;
        }
        if (lane == 7) s_base = atomicAdd(&g_alloc_ctr[ctr_idx], s);
        if (lane < 8) s_warp[lane] = s - orig;
    }
    __syncthreads();
    if (i < len) {
        int excl = (x - v) + s_warp[wid] + s_base;
        base[i] = excl;
        cur[i]  = excl;
    }
}

// ---------------- scatter nnz into both CSRs ----------------
__global__ __launch_bounds__(256) void scatter_kernel(const int* __restrict__ V, const int* __restrict__ E)
{
    int i = blockIdx.x * 256 + threadIdx.x;     // NNZ exact
    int v = __ldg(&V[i]);
    int e = __ldg(&E[i]);
    int pE = atomicAdd(&g_curE[e], 1);
    g_csrE_v[pE] = v;
    int pV = atomicAdd(&g_curV[v], 1);
    g_csrV_e[pV] = e;
}

// ---------------- edge aggregation: Yv2e[e] = elu( sum w_i*Xfeat[v_i] / sum w_i ) ----------------
__global__ __launch_bounds__(256) void edge_agg_kernel()
{
    const int e = blockIdx.x * 8 + (threadIdx.x >> 5);   // 25000*8 = 200000
    const int lane = threadIdx.x & 31;
    const int base = g_baseE[e];
    const int deg  = g_histE[e];
    float4 acc = make_float4(0.f, 0.f, 0.f, 0.f);
    float denom = 0.f;
    for (int j = 0; j < deg; j++) {
        int v = __ldg(&g_csrE_v[base + j]);              // warp-broadcast
        float s = g_scores[v];
        s = s > 0.f ? s : 0.2f * s;
        float w = expf(s);
        denom += w;
        float4 xf = *(const float4*)&g_Xfeat[(size_t)v * OUTC + lane * 4];
        acc.x += w * xf.x; acc.y += w * xf.y; acc.z += w * xf.z; acc.w += w * xf.w;
    }
    float inv = (deg > 0) ? (1.f / denom) : 0.f;
    float4 o;
    o.x = elu1(acc.x * inv); o.y = elu1(acc.y * inv);
    o.z = elu1(acc.z * inv); o.w = elu1(acc.w * inv);
    *(float4*)&g_Yv2e[(size_t)e * OUTC + lane * 4] = o;
}

// ---------------- node aggregation: Magg[n] = mean over incident edges of [Yv2e[e], S[e]] ----------------
__global__ __launch_bounds__(256) void node_agg_kernel(const float* __restrict__ S)
{
    const int n = blockIdx.x * 8 + (threadIdx.x >> 5);   // 12500*8 = 100000
    const int lane = threadIdx.x & 31;
    const int base = g_baseV[n];
    const int deg  = g_histV[n];
    float4 accY = make_float4(0.f, 0.f, 0.f, 0.f);
    float2 accS = make_float2(0.f, 0.f);
    for (int j = 0; j < deg; j++) {
        int e = __ldg(&g_csrV_e[base + j]);              // warp-broadcast
        float4 y = *(const float4*)&g_Yv2e[(size_t)e * OUTC + lane * 4];
        accY.x += y.x; accY.y += y.y; accY.z += y.z; accY.w += y.w;
        float2 s2 = *(const float2*)&S[(size_t)e * STAR_ + lane * 2];
        accS.x += s2.x; accS.y += s2.y;
    }
    float inv = 1.f / fmaxf((float)deg, 1.f);
    accY.x *= inv; accY.y *= inv; accY.z *= inv; accY.w *= inv;
    accS.x *= inv; accS.y *= inv;
    *(float4*)&g_Magg[(size_t)n * KTOT + lane * 4] = accY;
    *(float2*)&g_Magg[(size_t)n * KTOT + OUTC + lane * 2] = accS;
}

// ---------------- gemm_node: out = X_init + (deg>0 ? elu(Magg@Wt + bt) : 0) ----------------
// 64 rows x 128 cols; Wt staged in 3 k-chunks of 64 -> 87 KB smem -> 2 CTAs/SM.
__global__ __launch_bounds__(256, 2) void gemm_node_kernel(
    const float* __restrict__ Wt, const float* __restrict__ bt, float* __restrict__ out)
{
    extern __shared__ float sm[];
    float* sMT = sm;               // 192*72
    float* sW  = sm + 192 * 72;    // 64*132 (one k-chunk)

    const int tx = threadIdx.x;
    const int n0 = blockIdx.x * 64;

    #pragma unroll
    for (int it = 0; it < 12; it++) {
        int idx = tx + it * 256;       // 0..3071 = 64 rows * 48 float4
        int row = idx / 48;
        int kq  = idx % 48;
        int n = n0 + row;
        float4 v = make_float4(0.f, 0.f, 0.f, 0.f);
        if (n < N_NODES) v = *(const float4*)&g_Magg[(size_t)n * KTOT + kq * 4];
        int k = kq * 4;
        sMT[(k + 0) * 72 + row] = v.x;
        sMT[(k + 1) * 72 + row] = v.y;
        sMT[(k + 2) * 72 + row] = v.z;
        sMT[(k + 3) * 72 + row] = v.w;
    }

    const int c0 = (tx & 31) * 4;
    const int r0 = (tx >> 5) * 8;

    u64 a0[8], a1[8];
    #pragma unroll
    for (int i = 0; i < 8; i++) { a0[i] = 0ull; a1[i] = 0ull; }

    #pragma unroll
    for (int c = 0; c < 3; c++) {
        #pragma unroll
        for (int it = 0; it < 8; it++) {
            int idx = tx + it * 256;      // 64 rows * 32 float4
            int k  = idx >> 5;
            int cq = idx & 31;
            *(float4*)&sW[k * 132 + cq * 4] = *(const float4*)&Wt[(c * 64 + k) * OUTC + cq * 4];
        }
        __syncthreads();

        #pragma unroll 4
        for (int kk = 0; kk < 64; kk++) {
            int k = c * 64 + kk;
            ulonglong2 w2 = *(ulonglong2*)&sW[kk * 132 + c0];
            float4 xa = *(float4*)&sMT[k * 72 + r0];
            float4 xb = *(float4*)&sMT[k * 72 + r0 + 4];
            float xs[8] = {xa.x, xa.y, xa.z, xa.w, xb.x, xb.y, xb.z, xb.w};
            #pragma unroll
            for (int i = 0; i < 8; i++) {
                u64 xx = pack2(xs[i]);
                fma2(a0[i], xx, w2.x); fma2(a1[i], xx, w2.y);
            }
        }
        __syncthreads();
    }

    float4 bt4 = *(const float4*)&bt[c0];
    #pragma unroll
    for (int i = 0; i < 8; i++) {
        int n = n0 + r0 + i;
        if (n < N_NODES) {
            size_t oidx = (size_t)n * OUTC + c0;
            float4 o = *(const float4*)&out[oidx];           // X_init
            if (g_histV[n] > 0) {                            // isolated node -> elu(0)=0
                float2 p01 = unpack2(a0[i]), p23 = unpack2(a1[i]);
                o.x += elu1(p01.x + bt4.x);
                o.y += elu1(p01.y + bt4.y);
                o.z += elu1(p23.x + bt4.z);
                o.w += elu1(p23.y + bt4.w);
            }
            *(float4*)&out[oidx] = o;
        }
    }
}

// ---------------- launch ----------------
extern "C" void kernel_launch(void* const* d_in, const int* in_sizes, int n_in,
                              void* d_out, int out_size)
{
    const float* X  = (const float*)d_in[0];
    const int*   V  = (const int*)d_in[1];
    const int*   E  = (const int*)d_in[2];
    const float* S  = (const float*)d_in[3];
    const float* Wx = (const float*)d_in[4];
    const float* bx = (const float*)d_in[5];
    const float* Wv = (const float*)d_in[6];
    const float* bv = (const float*)d_in[7];
    const float* a  = (const float*)d_in[8];
    const float* Wt = (const float*)d_in[9];
    const float* bt = (const float*)d_in[10];
    float* out = (float*)d_out;

    void *p_histE, *p_histV, *p_ctr, *p_baseE, *p_curE, *p_baseV, *p_curV;
    cudaGetSymbolAddress(&p_histE, g_histE);
    cudaGetSymbolAddress(&p_histV, g_histV);
    cudaGetSymbolAddress(&p_ctr,   g_alloc_ctr);
    cudaGetSymbolAddress(&p_baseE, g_baseE);
    cudaGetSymbolAddress(&p_curE,  g_curE);
    cudaGetSymbolAddress(&p_baseV, g_baseV);
    cudaGetSymbolAddress(&p_curV,  g_curV);
    cudaMemsetAsync(p_histE, 0, N_EDGES * sizeof(int));
    cudaMemsetAsync(p_histV, 0, N_NODES * sizeof(int));
    cudaMemsetAsync(p_ctr,   0, 2 * sizeof(int));

    const int smem1 = (128 * 72 + 2 * 64 * 132) * (int)sizeof(float);   // 104448
    const int smem2 = (192 * 72 + 64 * 132) * (int)sizeof(float);       // 89088
    cudaFuncSetAttribute(gemm_x_kernel,    cudaFuncAttributeMaxDynamicSharedMemorySize, smem1);
    cudaFuncSetAttribute(gemm_node_kernel, cudaFuncAttributeMaxDynamicSharedMemorySize, smem2);

    hist_kernel<<<6250, 256>>>(V, E);
    gemm_x_kernel<<<1563, 256, smem1>>>(X, Wx, bx, Wv, bv, a, out);
    alloc_kernel<<<782, 256>>>((const int*)p_histE, (int*)p_baseE, (int*)p_curE, N_EDGES, 0);
    alloc_kernel<<<391, 256>>>((const int*)p_histV, (int*)p_baseV, (int*)p_curV, N_NODES, 1);
    scatter_kernel<<<6250, 256>>>(V, E);
    edge_agg_kernel<<<25000, 256>>>();
    node_agg_kernel<<<12500, 256>>>(S);
    gemm_node_kernel<<<1563, 256, smem2>>>(Wt, bt, out);
}